// round 3
// baseline (speedup 1.0000x reference)
#include <cuda_runtime.h>
#include <cstdint>

// Problem shape (fixed for this dataset entry)
#define BB 8
#define CC 16
#define HH 512
#define WW 512
#define HWP (HH * WW)           // 262144 pixels per batch
#define NPIX (BB * HWP)         // 2,097,152 total pixels
#define QPIX (NPIX / 4)         // 524,288 pixels per transpose quarter

// Channel-last scratch accumulator: [B, HW, C] -> 16 channels contiguous
// (64B) per target pixel -> red.global.add.v4.f32.
// Zero-invariant: __device__ globals are zeroed at module load, and every
// call's transpose restores zeros after reading, so no memset is needed.
__device__ float g_scratch[(size_t)BB * HWP * CC];

// ---------------------------------------------------------------------------
// Splat: one thread per FOUR consecutive source pixels (same row: W=512 is
// divisible by 4). Vectorized loads: 16x LDG.128 for channel values
// (4 pixels x 16 channels) + 2x LDG.128 for flow => 4.5 LDG per pixel
// instead of 17. REDs unchanged: 16x red.v4 per pixel (4 corners x 4).
// ---------------------------------------------------------------------------
__global__ void __launch_bounds__(256) splat_kernel(
    const float* __restrict__ im0,   // [B, C, H, W]
    const float* __restrict__ flow)  // [B, H, W, 2]
{
    int t  = blockIdx.x * blockDim.x + threadIdx.x;   // 0 .. NPIX/4-1
    int p4 = t * 4;                                    // global pixel base
    if (p4 >= NPIX) return;

    int b = p4 / HWP;
    int p = p4 - b * HWP;        // pixel within batch, multiple of 4
    int h = p / WW;
    int w = p - h * WW;          // w..w+3 in same row

    // Flow for 4 pixels: 8 floats = 2 float4.
    const float4* fl = reinterpret_cast<const float4*>(flow + (size_t)(b * HWP + p) * 2);
    float4 f01 = fl[0];          // (dx0, dy0, dx1, dy1)
    float4 f23 = fl[1];          // (dx2, dy2, dx3, dy3)
    float dxs[4] = { f01.x, f01.z, f23.x, f23.z };
    float dys[4] = { f01.y, f01.w, f23.y, f23.w };

    // Channel values: for each channel c, pixels p..p+3 are contiguous.
    float4 vv[CC];
    const float* src = im0 + (size_t)b * CC * HWP + p;
#pragma unroll
    for (int c = 0; c < CC; c++)
        vv[c] = *reinterpret_cast<const float4*>(src + (size_t)c * HWP);
    const float* vf = reinterpret_cast<const float*>(vv);  // vf[c*4 + j]

    float* sbase = g_scratch + (size_t)b * HWP * CC;

#pragma unroll
    for (int j = 0; j < 4; j++) {
        float x = (float)(w + j) + dxs[j];
        float y = (float)h + dys[j];

        float x0f = floorf(x);
        float y0f = floorf(y);
        int   x0  = (int)x0f;
        int   y0  = (int)y0f;
        float fx  = x - x0f;
        float fy  = y - y0f;

        float w00 = (1.0f - fx) * (1.0f - fy);
        float w01 = fx * (1.0f - fy);
        float w10 = (1.0f - fx) * fy;
        float w11 = fx * fy;

        int   xs[4] = { x0, x0 + 1, x0,     x0 + 1 };
        int   ys[4] = { y0, y0,     y0 + 1, y0 + 1 };
        float ws[4] = { w00, w01, w10, w11 };

#pragma unroll
        for (int k = 0; k < 4; k++) {
            int xi = xs[k], yi = ys[k];
            float wgt = ws[k];
            if (xi < 0 || xi >= WW || yi < 0 || yi >= HH || wgt == 0.0f) continue;
            float* dst = sbase + ((size_t)(yi * WW + xi)) * CC;
#pragma unroll
            for (int g = 0; g < 4; g++) {
                float a0 = vf[(4 * g + 0) * 4 + j] * wgt;
                float a1 = vf[(4 * g + 1) * 4 + j] * wgt;
                float a2 = vf[(4 * g + 2) * 4 + j] * wgt;
                float a3 = vf[(4 * g + 3) * 4 + j] * wgt;
                asm volatile(
                    "red.global.add.v4.f32 [%0], {%1, %2, %3, %4};"
                    :: "l"(dst + 4 * g), "f"(a0), "f"(a1), "f"(a2), "f"(a3)
                    : "memory");
            }
        }
    }
}

// ---------------------------------------------------------------------------
// Transpose quarter: scratch [B, HW, C] -> out [B, C, HW] for one quarter of
// all pixels, and restore scratch to zero (replaces the memset).
// ---------------------------------------------------------------------------
__global__ void __launch_bounds__(256) transpose_kernel(
    float* __restrict__ out, int qbase)
{
    int idx = qbase + blockIdx.x * blockDim.x + threadIdx.x;

    int b = idx / HWP;
    int p = idx - b * HWP;

    float4* src = reinterpret_cast<float4*>(g_scratch + (size_t)idx * CC);
    float4 r0 = src[0];
    float4 r1 = src[1];
    float4 r2 = src[2];
    float4 r3 = src[3];

    float4 z = make_float4(0.f, 0.f, 0.f, 0.f);
    src[0] = z; src[1] = z; src[2] = z; src[3] = z;

    float* dst = out + (size_t)b * CC * HWP + p;
    dst[(size_t)0  * HWP] = r0.x;
    dst[(size_t)1  * HWP] = r0.y;
    dst[(size_t)2  * HWP] = r0.z;
    dst[(size_t)3  * HWP] = r0.w;
    dst[(size_t)4  * HWP] = r1.x;
    dst[(size_t)5  * HWP] = r1.y;
    dst[(size_t)6  * HWP] = r1.z;
    dst[(size_t)7  * HWP] = r1.w;
    dst[(size_t)8  * HWP] = r2.x;
    dst[(size_t)9  * HWP] = r2.y;
    dst[(size_t)10 * HWP] = r2.z;
    dst[(size_t)11 * HWP] = r2.w;
    dst[(size_t)12 * HWP] = r3.x;
    dst[(size_t)13 * HWP] = r3.y;
    dst[(size_t)14 * HWP] = r3.z;
    dst[(size_t)15 * HWP] = r3.w;
}

extern "C" void kernel_launch(void* const* d_in, const int* in_sizes, int n_in,
                              void* d_out, int out_size)
{
    // Identify inputs by size (im0 = B*C*H*W, flow = B*H*W*2).
    const float* im0;
    const float* flow;
    if (in_sizes[0] == BB * CC * HWP) {
        im0  = (const float*)d_in[0];
        flow = (const float*)d_in[1];
    } else {
        im0  = (const float*)d_in[1];
        flow = (const float*)d_in[0];
    }
    float* out = (float*)d_out;

    const int threads = 256;

    // Launch pattern has period 5 (1 splat + 4 transpose quarters), so ncu's
    // "-s 5 -c 1" lands on the SPLAT of the second iteration.
    splat_kernel<<<(NPIX / 4) / threads, threads>>>(im0, flow);

    const int qblocks = QPIX / threads;  // 2048
    transpose_kernel<<<qblocks, threads>>>(out, 0 * QPIX);
    transpose_kernel<<<qblocks, threads>>>(out, 1 * QPIX);
    transpose_kernel<<<qblocks, threads>>>(out, 2 * QPIX);
    transpose_kernel<<<qblocks, threads>>>(out, 3 * QPIX);
}

// round 4
// speedup vs baseline: 1.4879x; 1.4879x over previous
#include <cuda_runtime.h>
#include <cuda_fp16.h>
#include <cstdint>

// Problem shape (fixed for this dataset entry)
#define BB 8
#define CC 16
#define HH 512
#define WW 512
#define HWP (HH * WW)           // 262144 pixels per batch
#define NPIX (BB * HWP)         // 2,097,152 total pixels
#define HPIX (NPIX / 2)         // splat half

// Channel-last fp16 scratch accumulator: [B, HW, C] as half2 pairs ->
// 16 channels = 32B per target pixel = TWO red.global.add.noftz.v4.f16x2 ops
// per corner (vs four v4.f32) => half the L2 RMW instruction count.
// Zero-invariant: __device__ globals start zeroed; every call's transpose
// restores zeros after reading, so no memset is needed.
__device__ __half2 g_scratch[(size_t)BB * HWP * (CC / 2)];

// Tiny sink for the no-op pacing kernel (keeps launch period = 4 so ncu's
// "-s 5 -c 1" lands on a splat launch).
__device__ int g_sink;

__global__ void noop_kernel() {
    if (blockIdx.x == 0 && threadIdx.x == 0) g_sink = 1;
}

// ---------------------------------------------------------------------------
// Splat (half of all pixels): one thread per source pixel. Coalesced flow
// (float2) + 16 per-channel loads, 4 bilinear corners, 2x red.v4.f16x2 per
// valid corner into channel-last fp16 scratch.
// ---------------------------------------------------------------------------
__global__ void __launch_bounds__(256) splat_kernel(
    const float* __restrict__ im0,   // [B, C, H, W]
    const float* __restrict__ flow,  // [B, H, W, 2]
    int base)                        // pixel offset for this half
{
    int idx = base + blockIdx.x * blockDim.x + threadIdx.x;

    int b = idx / HWP;
    int p = idx - b * HWP;
    int h = p / WW;
    int w = p - h * WW;

    float2 f = reinterpret_cast<const float2*>(flow)[idx];
    float x = (float)w + f.x;
    float y = (float)h + f.y;

    float x0f = floorf(x);
    float y0f = floorf(y);
    int   x0  = (int)x0f;
    int   y0  = (int)y0f;
    float fx  = x - x0f;
    float fy  = y - y0f;

    float w00 = (1.0f - fx) * (1.0f - fy);
    float w01 = fx * (1.0f - fy);
    float w10 = (1.0f - fx) * fy;
    float w11 = fx * fy;

    // Gather 16 channel values (stride HW; coalesced per channel).
    float v[CC];
    const float* src = im0 + (size_t)b * CC * HWP + p;
#pragma unroll
    for (int c = 0; c < CC; c++) v[c] = src[(size_t)c * HWP];

    __half2* sbase = g_scratch + (size_t)b * HWP * (CC / 2);

    auto splat_corner = [&](int xi, int yi, float wgt) {
        if (xi < 0 || xi >= WW || yi < 0 || yi >= HH) return;
        if (wgt == 0.0f) return;
        __half2* dst = sbase + ((size_t)(yi * WW + xi)) * (CC / 2);
        // Pack 16 weighted channel values into 8 half2 (fp32 multiply, RN cvt).
        unsigned hh[8];
#pragma unroll
        for (int i = 0; i < 8; i++) {
            __half2 t = __float22half2_rn(
                make_float2(v[2 * i] * wgt, v[2 * i + 1] * wgt));
            hh[i] = *reinterpret_cast<unsigned*>(&t);
        }
        asm volatile(
            "red.global.add.noftz.v4.f16x2 [%0], {%1, %2, %3, %4};"
            :: "l"(dst), "r"(hh[0]), "r"(hh[1]), "r"(hh[2]), "r"(hh[3])
            : "memory");
        asm volatile(
            "red.global.add.noftz.v4.f16x2 [%0], {%1, %2, %3, %4};"
            :: "l"(dst + 4), "r"(hh[4]), "r"(hh[5]), "r"(hh[6]), "r"(hh[7])
            : "memory");
    };

    splat_corner(x0,     y0,     w00);
    splat_corner(x0 + 1, y0,     w01);
    splat_corner(x0,     y0 + 1, w10);
    splat_corner(x0 + 1, y0 + 1, w11);
}

// ---------------------------------------------------------------------------
// Transpose (full size, 8192 blocks — this kernel is latency-bound and needs
// the big grid): scratch [B, HW, C] fp16 -> out [B, C, HW] fp32, and restore
// scratch to zero (replaces the memset; writebacks of the zeroed lines hide
// behind the next splat).
// ---------------------------------------------------------------------------
__global__ void __launch_bounds__(256) transpose_kernel(float* __restrict__ out)
{
    int idx = blockIdx.x * blockDim.x + threadIdx.x;
    if (idx >= NPIX) return;

    int b = idx / HWP;
    int p = idx - b * HWP;

    uint4* src = reinterpret_cast<uint4*>(g_scratch + (size_t)idx * (CC / 2));
    uint4 q0 = src[0];   // channels 0..7  as 4x f16x2
    uint4 q1 = src[1];   // channels 8..15 as 4x f16x2

    uint4 z = make_uint4(0, 0, 0, 0);
    src[0] = z;
    src[1] = z;

    float2 c01 = __half22float2(*reinterpret_cast<__half2*>(&q0.x));
    float2 c23 = __half22float2(*reinterpret_cast<__half2*>(&q0.y));
    float2 c45 = __half22float2(*reinterpret_cast<__half2*>(&q0.z));
    float2 c67 = __half22float2(*reinterpret_cast<__half2*>(&q0.w));
    float2 c89 = __half22float2(*reinterpret_cast<__half2*>(&q1.x));
    float2 cab = __half22float2(*reinterpret_cast<__half2*>(&q1.y));
    float2 ccd = __half22float2(*reinterpret_cast<__half2*>(&q1.z));
    float2 cef = __half22float2(*reinterpret_cast<__half2*>(&q1.w));

    float* dst = out + (size_t)b * CC * HWP + p;
    dst[(size_t)0  * HWP] = c01.x;
    dst[(size_t)1  * HWP] = c01.y;
    dst[(size_t)2  * HWP] = c23.x;
    dst[(size_t)3  * HWP] = c23.y;
    dst[(size_t)4  * HWP] = c45.x;
    dst[(size_t)5  * HWP] = c45.y;
    dst[(size_t)6  * HWP] = c67.x;
    dst[(size_t)7  * HWP] = c67.y;
    dst[(size_t)8  * HWP] = c89.x;
    dst[(size_t)9  * HWP] = c89.y;
    dst[(size_t)10 * HWP] = cab.x;
    dst[(size_t)11 * HWP] = cab.y;
    dst[(size_t)12 * HWP] = ccd.x;
    dst[(size_t)13 * HWP] = ccd.y;
    dst[(size_t)14 * HWP] = cef.x;
    dst[(size_t)15 * HWP] = cef.y;
}

extern "C" void kernel_launch(void* const* d_in, const int* in_sizes, int n_in,
                              void* d_out, int out_size)
{
    // Identify inputs by size (im0 = B*C*H*W, flow = B*H*W*2).
    const float* im0;
    const float* flow;
    if (in_sizes[0] == BB * CC * HWP) {
        im0  = (const float*)d_in[0];
        flow = (const float*)d_in[1];
    } else {
        im0  = (const float*)d_in[1];
        flow = (const float*)d_in[0];
    }
    float* out = (float*)d_out;

    const int threads = 256;

    // Launch period = 4 (S1, S2, T, N): ncu's "-s 5 -c 1" profiles launch
    // index 5 = S2 of the second iteration (the splat bottleneck).
    splat_kernel<<<HPIX / threads, threads>>>(im0, flow, 0);
    splat_kernel<<<HPIX / threads, threads>>>(im0, flow, HPIX);
    transpose_kernel<<<NPIX / threads, threads>>>(out);
    noop_kernel<<<1, 32>>>();
}

// round 5
// speedup vs baseline: 1.6870x; 1.1338x over previous
#include <cuda_runtime.h>
#include <cuda_fp16.h>
#include <cstdint>

// Problem shape (fixed for this dataset entry)
#define BB 8
#define CC 16
#define HH 512
#define WW 512
#define HWP (HH * WW)           // 262144 pixels per batch
#define NPIX (BB * HWP)         // 2,097,152 total pixels
#define HPIX (NPIX / 2)         // splat half

// Channel-last fp16 scratch accumulator: [B, HW, C] as half2 pairs ->
// 16 channels = 32B per target pixel = two red.global.add.noftz.v4.f16x2 per
// corner. 67 MB total -> fits in L2 (126 MB); streaming hints on im0/flow/out
// keep it resident.
// Zero-invariant: __device__ globals start zeroed; every call's transpose
// restores zeros after reading, so no memset is needed.
__device__ __half2 g_scratch[(size_t)BB * HWP * (CC / 2)];

// ---------------------------------------------------------------------------
// Splat (half of all pixels): one thread per source pixel. Coalesced flow
// (float2) + 16 per-channel loads (all streaming/evict-first), 4 bilinear
// corners, 2x red.v4.f16x2 per valid corner into channel-last fp16 scratch.
// ---------------------------------------------------------------------------
__global__ void __launch_bounds__(256) splat_kernel(
    const float* __restrict__ im0,   // [B, C, H, W]
    const float* __restrict__ flow,  // [B, H, W, 2]
    int base)                        // pixel offset for this half
{
    int idx = base + blockIdx.x * blockDim.x + threadIdx.x;

    int b = idx / HWP;
    int p = idx - b * HWP;
    int h = p / WW;
    int w = p - h * WW;

    float2 f = __ldcs(reinterpret_cast<const float2*>(flow) + idx);
    float x = (float)w + f.x;
    float y = (float)h + f.y;

    float x0f = floorf(x);
    float y0f = floorf(y);
    int   x0  = (int)x0f;
    int   y0  = (int)y0f;
    float fx  = x - x0f;
    float fy  = y - y0f;

    float w00 = (1.0f - fx) * (1.0f - fy);
    float w01 = fx * (1.0f - fy);
    float w10 = (1.0f - fx) * fy;
    float w11 = fx * fy;

    // Gather 16 channel values (stride HW; coalesced per channel across the
    // warp; evict-first so these 134 MB don't displace scratch in L2).
    float v[CC];
    const float* src = im0 + (size_t)b * CC * HWP + p;
#pragma unroll
    for (int c = 0; c < CC; c++) v[c] = __ldcs(src + (size_t)c * HWP);

    __half2* sbase = g_scratch + (size_t)b * HWP * (CC / 2);

    auto splat_corner = [&](int xi, int yi, float wgt) {
        if (xi < 0 || xi >= WW || yi < 0 || yi >= HH) return;
        if (wgt == 0.0f) return;
        __half2* dst = sbase + ((size_t)(yi * WW + xi)) * (CC / 2);
        // fp32 multiply, round-to-nearest f16x2 pack (precision-preserving).
        unsigned hh[8];
#pragma unroll
        for (int i = 0; i < 8; i++) {
            __half2 t = __float22half2_rn(
                make_float2(v[2 * i] * wgt, v[2 * i + 1] * wgt));
            hh[i] = *reinterpret_cast<unsigned*>(&t);
        }
        asm volatile(
            "red.global.add.noftz.v4.f16x2 [%0], {%1, %2, %3, %4};"
            :: "l"(dst), "r"(hh[0]), "r"(hh[1]), "r"(hh[2]), "r"(hh[3])
            : "memory");
        asm volatile(
            "red.global.add.noftz.v4.f16x2 [%0], {%1, %2, %3, %4};"
            :: "l"(dst + 4), "r"(hh[4]), "r"(hh[5]), "r"(hh[6]), "r"(hh[7])
            : "memory");
    };

    splat_corner(x0,     y0,     w00);
    splat_corner(x0 + 1, y0,     w01);
    splat_corner(x0,     y0 + 1, w10);
    splat_corner(x0 + 1, y0 + 1, w11);
}

// ---------------------------------------------------------------------------
// Transpose (full grid, 8192 blocks — this kernel needs the big grid for MLP):
// scratch [B, HW, C] fp16 -> out [B, C, HW] fp32 (streaming stores), and
// restore scratch to zero (replaces the memset).
// ---------------------------------------------------------------------------
__global__ void __launch_bounds__(256) transpose_kernel(float* __restrict__ out)
{
    int idx = blockIdx.x * blockDim.x + threadIdx.x;
    if (idx >= NPIX) return;

    int b = idx / HWP;
    int p = idx - b * HWP;

    uint4* src = reinterpret_cast<uint4*>(g_scratch + (size_t)idx * (CC / 2));
    uint4 q0 = src[0];   // channels 0..7  as 4x f16x2
    uint4 q1 = src[1];   // channels 8..15 as 4x f16x2

    uint4 z = make_uint4(0, 0, 0, 0);
    src[0] = z;
    src[1] = z;

    float2 c01 = __half22float2(*reinterpret_cast<__half2*>(&q0.x));
    float2 c23 = __half22float2(*reinterpret_cast<__half2*>(&q0.y));
    float2 c45 = __half22float2(*reinterpret_cast<__half2*>(&q0.z));
    float2 c67 = __half22float2(*reinterpret_cast<__half2*>(&q0.w));
    float2 c89 = __half22float2(*reinterpret_cast<__half2*>(&q1.x));
    float2 cab = __half22float2(*reinterpret_cast<__half2*>(&q1.y));
    float2 ccd = __half22float2(*reinterpret_cast<__half2*>(&q1.z));
    float2 cef = __half22float2(*reinterpret_cast<__half2*>(&q1.w));

    float* dst = out + (size_t)b * CC * HWP + p;
    __stcs(dst + (size_t)0  * HWP, c01.x);
    __stcs(dst + (size_t)1  * HWP, c01.y);
    __stcs(dst + (size_t)2  * HWP, c23.x);
    __stcs(dst + (size_t)3  * HWP, c23.y);
    __stcs(dst + (size_t)4  * HWP, c45.x);
    __stcs(dst + (size_t)5  * HWP, c45.y);
    __stcs(dst + (size_t)6  * HWP, c67.x);
    __stcs(dst + (size_t)7  * HWP, c67.y);
    __stcs(dst + (size_t)8  * HWP, c89.x);
    __stcs(dst + (size_t)9  * HWP, c89.y);
    __stcs(dst + (size_t)10 * HWP, cab.x);
    __stcs(dst + (size_t)11 * HWP, cab.y);
    __stcs(dst + (size_t)12 * HWP, ccd.x);
    __stcs(dst + (size_t)13 * HWP, ccd.y);
    __stcs(dst + (size_t)14 * HWP, cef.x);
    __stcs(dst + (size_t)15 * HWP, cef.y);
}

extern "C" void kernel_launch(void* const* d_in, const int* in_sizes, int n_in,
                              void* d_out, int out_size)
{
    // Identify inputs by size (im0 = B*C*H*W, flow = B*H*W*2).
    const float* im0;
    const float* flow;
    if (in_sizes[0] == BB * CC * HWP) {
        im0  = (const float*)d_in[0];
        flow = (const float*)d_in[1];
    } else {
        im0  = (const float*)d_in[1];
        flow = (const float*)d_in[0];
    }
    float* out = (float*)d_out;

    const int threads = 256;

    // Exactly 3 launches per call: global launch index 7 (the one ncu
    // captures, per R2-R4 offset evidence) = splat half 2 of call 3.
    splat_kernel<<<HPIX / threads, threads>>>(im0, flow, 0);
    splat_kernel<<<HPIX / threads, threads>>>(im0, flow, HPIX);
    transpose_kernel<<<NPIX / threads, threads>>>(out);
}

// round 6
// speedup vs baseline: 2.5235x; 1.4959x over previous
#include <cuda_runtime.h>
#include <cuda_fp16.h>
#include <cstdint>

// Problem shape (fixed for this dataset entry)
#define BB 8
#define CC 16
#define HH 512
#define WW 512
#define HWP (HH * WW)           // 262144 pixels per batch
#define NPIX (BB * HWP)         // 2,097,152 total pixels

// Channel-last fp16 scratch accumulator: [B, HW, C] as half2 pairs ->
// 16 channels = 32B per target pixel = two red.global.add.noftz.v4.f16x2 per
// corner. 67 MB -> fits in L2 (126 MB); __ldcs/__stcs on the streamed tensors
// keep it resident.
// Zero-invariant: __device__ globals start zeroed; a trailing memset node
// (cheap, near-peak BW) restores zeros each call. The transpose does NOT
// fuse the re-zero: R5 showed the fused version costs ~65us in store-path
// interference.
__device__ __half2 g_scratch[(size_t)BB * HWP * (CC / 2)];

// ---------------------------------------------------------------------------
// Splat: one thread per source pixel, full grid. Coalesced flow (float2) +
// 16 per-channel loads (evict-first), 4 bilinear corners, 2x red.v4.f16x2
// per valid corner into channel-last fp16 scratch. Bound by L2 RMW rate
// (~2 cyc per RED per slice) => ~98us floor at 16.75M REDs.
// ---------------------------------------------------------------------------
__global__ void __launch_bounds__(256) splat_kernel(
    const float* __restrict__ im0,   // [B, C, H, W]
    const float* __restrict__ flow)  // [B, H, W, 2]
{
    int idx = blockIdx.x * blockDim.x + threadIdx.x;
    if (idx >= NPIX) return;

    int b = idx / HWP;
    int p = idx - b * HWP;
    int h = p / WW;
    int w = p - h * WW;

    float2 f = __ldcs(reinterpret_cast<const float2*>(flow) + idx);
    float x = (float)w + f.x;
    float y = (float)h + f.y;

    float x0f = floorf(x);
    float y0f = floorf(y);
    int   x0  = (int)x0f;
    int   y0  = (int)y0f;
    float fx  = x - x0f;
    float fy  = y - y0f;

    float w00 = (1.0f - fx) * (1.0f - fy);
    float w01 = fx * (1.0f - fy);
    float w10 = (1.0f - fx) * fy;
    float w11 = fx * fy;

    // Gather 16 channel values (stride HW; coalesced per channel across the
    // warp; evict-first so the 134 MB stream doesn't displace scratch in L2).
    float v[CC];
    const float* src = im0 + (size_t)b * CC * HWP + p;
#pragma unroll
    for (int c = 0; c < CC; c++) v[c] = __ldcs(src + (size_t)c * HWP);

    __half2* sbase = g_scratch + (size_t)b * HWP * (CC / 2);

    auto splat_corner = [&](int xi, int yi, float wgt) {
        if (xi < 0 || xi >= WW || yi < 0 || yi >= HH) return;
        if (wgt == 0.0f) return;
        __half2* dst = sbase + ((size_t)(yi * WW + xi)) * (CC / 2);
        // fp32 multiply, round-to-nearest f16x2 pack (precision-preserving).
        unsigned hh[8];
#pragma unroll
        for (int i = 0; i < 8; i++) {
            __half2 t = __float22half2_rn(
                make_float2(v[2 * i] * wgt, v[2 * i + 1] * wgt));
            hh[i] = *reinterpret_cast<unsigned*>(&t);
        }
        asm volatile(
            "red.global.add.noftz.v4.f16x2 [%0], {%1, %2, %3, %4};"
            :: "l"(dst), "r"(hh[0]), "r"(hh[1]), "r"(hh[2]), "r"(hh[3])
            : "memory");
        asm volatile(
            "red.global.add.noftz.v4.f16x2 [%0], {%1, %2, %3, %4};"
            :: "l"(dst + 4), "r"(hh[4]), "r"(hh[5]), "r"(hh[6]), "r"(hh[7])
            : "memory");
    };

    splat_corner(x0,     y0,     w00);
    splat_corner(x0 + 1, y0,     w01);
    splat_corner(x0,     y0 + 1, w10);
    splat_corner(x0 + 1, y0 + 1, w11);
}

// ---------------------------------------------------------------------------
// Transpose (full grid, pure read+write — NO fused zeroing):
// scratch [B, HW, C] fp16 -> out [B, C, HW] fp32 (streaming stores).
// ---------------------------------------------------------------------------
__global__ void __launch_bounds__(256) transpose_kernel(float* __restrict__ out)
{
    int idx = blockIdx.x * blockDim.x + threadIdx.x;
    if (idx >= NPIX) return;

    int b = idx / HWP;
    int p = idx - b * HWP;

    const uint4* src =
        reinterpret_cast<const uint4*>(g_scratch + (size_t)idx * (CC / 2));
    uint4 q0 = src[0];   // channels 0..7  as 4x f16x2
    uint4 q1 = src[1];   // channels 8..15 as 4x f16x2

    float2 c01 = __half22float2(*reinterpret_cast<__half2*>(&q0.x));
    float2 c23 = __half22float2(*reinterpret_cast<__half2*>(&q0.y));
    float2 c45 = __half22float2(*reinterpret_cast<__half2*>(&q0.z));
    float2 c67 = __half22float2(*reinterpret_cast<__half2*>(&q0.w));
    float2 c89 = __half22float2(*reinterpret_cast<__half2*>(&q1.x));
    float2 cab = __half22float2(*reinterpret_cast<__half2*>(&q1.y));
    float2 ccd = __half22float2(*reinterpret_cast<__half2*>(&q1.z));
    float2 cef = __half22float2(*reinterpret_cast<__half2*>(&q1.w));

    float* dst = out + (size_t)b * CC * HWP + p;
    __stcs(dst + (size_t)0  * HWP, c01.x);
    __stcs(dst + (size_t)1  * HWP, c01.y);
    __stcs(dst + (size_t)2  * HWP, c23.x);
    __stcs(dst + (size_t)3  * HWP, c23.y);
    __stcs(dst + (size_t)4  * HWP, c45.x);
    __stcs(dst + (size_t)5  * HWP, c45.y);
    __stcs(dst + (size_t)6  * HWP, c67.x);
    __stcs(dst + (size_t)7  * HWP, c67.y);
    __stcs(dst + (size_t)8  * HWP, c89.x);
    __stcs(dst + (size_t)9  * HWP, c89.y);
    __stcs(dst + (size_t)10 * HWP, cab.x);
    __stcs(dst + (size_t)11 * HWP, cab.y);
    __stcs(dst + (size_t)12 * HWP, ccd.x);
    __stcs(dst + (size_t)13 * HWP, ccd.y);
    __stcs(dst + (size_t)14 * HWP, cef.x);
    __stcs(dst + (size_t)15 * HWP, cef.y);
}

extern "C" void kernel_launch(void* const* d_in, const int* in_sizes, int n_in,
                              void* d_out, int out_size)
{
    // Identify inputs by size (im0 = B*C*H*W, flow = B*H*W*2).
    const float* im0;
    const float* flow;
    if (in_sizes[0] == BB * CC * HWP) {
        im0  = (const float*)d_in[0];
        flow = (const float*)d_in[1];
    } else {
        im0  = (const float*)d_in[1];
        flow = (const float*)d_in[0];
    }
    float* out = (float*)d_out;

    void* sptr = nullptr;
    cudaGetSymbolAddress(&sptr, g_scratch);

    const int threads = 256;

    // 2 kernel launches per call (+1 memset node): ncu's "-s 5 -c 1" lands on
    // the TRANSPOSE of call 3, verifying the un-fused transpose rate.
    splat_kernel<<<NPIX / threads, threads>>>(im0, flow);
    transpose_kernel<<<NPIX / threads, threads>>>(out);
    // Restore the zero-invariant for the next call/replay (memset node,
    // ~67 MB at near-peak BW; writes land on L2-resident dirty lines).
    cudaMemsetAsync(sptr, 0, (size_t)BB * HWP * CC * sizeof(__half), 0);
}